// round 14
// baseline (speedup 1.0000x reference)
#include <cuda_runtime.h>
#include <cuda_fp16.h>
#include <cstdint>

#define NTH 256
#define TZ 64

#define OFF_W 0
#define OFF_FA 65536
#define OFF_FB 32768
#define OFF_ST 98304
#define SMEM_BYTES 114688

__device__ int g_tp_ctr[2];

__global__ void tp_init_ctr() {
    if (threadIdx.x < 2) g_tp_ctr[threadIdx.x] = 0;
}

static __device__ __forceinline__ uint32_t s2u(const void* p) {
    uint32_t a;
    asm("{ .reg .u64 t; cvta.to.shared.u64 t, %1; cvt.u32.u64 %0, t; }"
        : "=r"(a) : "l"(p));
    return a;
}

static __device__ __forceinline__ uint32_t pkh2(float a, float b) {
    __half2 h = __floats2half2_rn(a, b);
    return *reinterpret_cast<uint32_t*>(&h);
}

static __device__ __forceinline__ void ldsm4(uint32_t addr, uint32_t r[4]) {
    asm volatile("ldmatrix.sync.aligned.m8n8.x4.shared.b16 {%0,%1,%2,%3}, [%4];"
                 : "=r"(r[0]), "=r"(r[1]), "=r"(r[2]), "=r"(r[3])
                 : "r"(addr));
}

static __device__ __forceinline__ void mma16816(float d[4], const uint32_t a[4],
                                                uint32_t b0, uint32_t b1) {
    asm volatile(
        "mma.sync.aligned.m16n8k16.row.col.f32.f16.f16.f32 "
        "{%0,%1,%2,%3}, {%4,%5,%6,%7}, {%8,%9}, {%0,%1,%2,%3};"
        : "+f"(d[0]), "+f"(d[1]), "+f"(d[2]), "+f"(d[3])
        : "r"(a[0]), "r"(a[1]), "r"(a[2]), "r"(a[3]), "r"(b0), "r"(b1));
}

template <int NKS, int RB>
static __device__ __forceinline__ void gemm16x32(uint32_t fbase, uint32_t wbase,
                                                 int zb, int wn, int lane,
                                                 float d[4][4]) {
    const int arow = zb + (lane & 15);
    const int ach = lane >> 4;
    const int brow0 = 32 * wn + ((lane >> 4) << 3) + (lane & 7);
    const int bch = (lane >> 3) & 1;
#pragma unroll
    for (int ks = 0; ks < NKS; ++ks) {
        uint32_t a[4];
        ldsm4(fbase + arow * RB + (((ks * 2 + ach) ^ (arow & 7)) << 4), a);
        uint32_t b[2][4];
#pragma unroll
        for (int nb = 0; nb < 2; ++nb) {
            int row = brow0 + 16 * nb;
            ldsm4(wbase + row * RB + (((ks * 2 + bch) ^ (row & 7)) << 4), b[nb]);
        }
#pragma unroll
        for (int nt = 0; nt < 4; ++nt)
            mma16816(d[nt], a, b[nt >> 1][(nt & 1) * 2],
                     b[nt >> 1][(nt & 1) * 2 + 1]);
    }
}

__global__ void __launch_bounds__(NTH, 2)
tp_hmma12(const float* __restrict__ x1, const float* __restrict__ x2,
          const float* __restrict__ wts, float* __restrict__ out,
          int Z, int NT, int NA, int NB) {
    extern __shared__ char smc[];
    __shared__ int s_t;
    const uint32_t sb = s2u(smc);
    const int tid = threadIdx.x;
    const int lane = tid & 31, wid = tid >> 5;
    const int zm = wid & 1, wn = wid >> 1;
    const bool roleA = (int)blockIdx.x < NA;
    const float inv16 = 0.0625f;
    const float c2 = 0.03608439182435161f;  // 1/(16*sqrt(3))

    // ---- weights into smem (fp16, [w][k], swizzled) ----
    if (roleA) {
        for (int i = tid; i < 4096; i += NTH) {
            int w = i >> 5, c = i & 31;
            const float* src = (c < 16) ? wts : (wts + 49152);  // W0 / W3
            int u0 = (c & 15) * 8;
            uint32_t h[4];
#pragma unroll
            for (int j = 0; j < 4; ++j)
                h[j] = pkh2(src[(u0 + 2 * j) * 128 + w],
                            src[(u0 + 2 * j + 1) * 128 + w]);
            *(uint4*)(smc + OFF_W + w * 512 + ((c ^ (w & 7)) << 4)) =
                make_uint4(h[0], h[1], h[2], h[3]);
        }
    } else {
        for (int i = tid; i < 2048; i += NTH) {
            int w = i >> 4, c = i & 15;
            int u0 = c * 8;
            const float* s1 = wts + 16384;  // W1
            const float* s2 = wts + 32768;  // W2
            uint32_t h1[4], h2[4];
#pragma unroll
            for (int j = 0; j < 4; ++j) {
                h1[j] = pkh2(s1[(u0 + 2 * j) * 128 + w],
                             s1[(u0 + 2 * j + 1) * 128 + w]);
                h2[j] = pkh2(s2[(u0 + 2 * j) * 128 + w],
                             s2[(u0 + 2 * j + 1) * 128 + w]);
            }
            uint32_t so = (uint32_t)(w * 256 + ((c ^ (w & 7)) << 4));
            *(uint4*)(smc + OFF_W + so) = make_uint4(h1[0], h1[1], h1[2], h1[3]);
            *(uint4*)(smc + OFF_W + 32768 + so) =
                make_uint4(h2[0], h2[1], h2[2], h2[3]);
        }
    }

    if (roleA) {
        __syncthreads();
        // ---- preload W0-half B fragments into registers ----
        uint32_t w0f[8][8];
        {
            const int brow0 = 32 * wn + ((lane >> 4) << 3) + (lane & 7);
            const int bch = (lane >> 3) & 1;
#pragma unroll
            for (int ks = 0; ks < 8; ++ks)
#pragma unroll
                for (int nb = 0; nb < 2; ++nb) {
                    int row = brow0 + 16 * nb;
                    ldsm4(sb + OFF_W + row * 512 +
                              (((ks * 2 + bch) ^ (row & 7)) << 4),
                          &w0f[ks][4 * nb]);
                }
        }
        const int zb = 32 * zm;
        if (tid == 0) s_t = atomicAdd(&g_tp_ctr[0], 1);
        __syncthreads();
        while (true) {
            const int t = s_t;
            if (t >= NT) break;
            const int z0t = t * TZ;
            const int zv = min(TZ, Z - z0t);

            // a-part: k chunks 0..15 (non-divergent)
#pragma unroll 2
            for (int it = 0; it < 4; ++it) {
                int i = tid + it * NTH;
                int z = i >> 4, c = i & 15;
                uint4 wv = make_uint4(0, 0, 0, 0);
                if (z < zv) {
                    float s = inv16 * __ldg(x2 + (size_t)(z0t + z) * 4);
                    const float* ap = x1 + (size_t)(z0t + z) * 512 + 8 * c;
                    float4 p0 = *(const float4*)(ap);
                    float4 p1 = *(const float4*)(ap + 4);
                    wv = make_uint4(pkh2(s * p0.x, s * p0.y),
                                    pkh2(s * p0.z, s * p0.w),
                                    pkh2(s * p1.x, s * p1.y),
                                    pkh2(s * p1.z, s * p1.w));
                }
                *(uint4*)(smc + OFF_FA + z * 512 + ((c ^ (z & 7)) << 4)) = wv;
            }
            // b-part: k chunks 16..31 (non-divergent)
#pragma unroll 1
            for (int it = 0; it < 4; ++it) {
                int i = tid + it * NTH;
                int z = i >> 4, c = (i & 15) + 16;
                uint4 wv = make_uint4(0, 0, 0, 0);
                if (z < zv) {
                    float4 xv = __ldg((const float4*)(x2 + (size_t)(z0t + z) * 4));
                    const float* bp =
                        x1 + (size_t)(z0t + z) * 512 + 128 + 24 * (c - 16);
                    float arr[24];
#pragma unroll
                    for (int q = 0; q < 6; ++q)
                        *(float4*)(arr + 4 * q) = *(const float4*)(bp + 4 * q);
                    float f[8];
#pragma unroll
                    for (int j = 0; j < 8; ++j)
                        f[j] = c2 * (arr[3 * j] * xv.y + arr[3 * j + 1] * xv.z +
                                     arr[3 * j + 2] * xv.w);
                    wv = make_uint4(pkh2(f[0], f[1]), pkh2(f[2], f[3]),
                                    pkh2(f[4], f[5]), pkh2(f[6], f[7]));
                }
                *(uint4*)(smc + OFF_FA + z * 512 + ((c ^ (z & 7)) << 4)) = wv;
            }
            __syncthreads();

            float d[2][4][4];
#pragma unroll
            for (int mt = 0; mt < 2; ++mt)
#pragma unroll
                for (int nt = 0; nt < 4; ++nt)
#pragma unroll
                    for (int r = 0; r < 4; ++r) d[mt][nt][r] = 0.0f;
            {
                const int arow0 = zb + (lane & 15);
                const int ach = lane >> 4;
                const int brow0 = 32 * wn + ((lane >> 4) << 3) + (lane & 7);
                const int bch = (lane >> 3) & 1;
#pragma unroll
                for (int ks = 0; ks < 8; ++ks) {
                    uint32_t a[2][4];
#pragma unroll
                    for (int mt = 0; mt < 2; ++mt) {
                        int row = arow0 + 16 * mt;
                        ldsm4(sb + OFF_FA + row * 512 +
                                  (((ks * 2 + ach) ^ (row & 7)) << 4),
                              a[mt]);
                    }
#pragma unroll
                    for (int mt = 0; mt < 2; ++mt)
#pragma unroll
                        for (int nt = 0; nt < 4; ++nt)
                            mma16816(d[mt][nt], a[mt],
                                     w0f[ks][(nt >> 1) * 4 + (nt & 1) * 2],
                                     w0f[ks][(nt >> 1) * 4 + (nt & 1) * 2 + 1]);
                }
#pragma unroll
                for (int ks = 8; ks < 16; ++ks) {
                    uint32_t a[2][4];
#pragma unroll
                    for (int mt = 0; mt < 2; ++mt) {
                        int row = arow0 + 16 * mt;
                        ldsm4(sb + OFF_FA + row * 512 +
                                  (((ks * 2 + ach) ^ (row & 7)) << 4),
                              a[mt]);
                    }
                    uint32_t b[2][4];
#pragma unroll
                    for (int nb = 0; nb < 2; ++nb) {
                        int row = brow0 + 16 * nb;
                        ldsm4(sb + OFF_W + row * 512 +
                                  (((ks * 2 + bch) ^ (row & 7)) << 4),
                              b[nb]);
                    }
#pragma unroll
                    for (int mt = 0; mt < 2; ++mt)
#pragma unroll
                        for (int nt = 0; nt < 4; ++nt)
                            mma16816(d[mt][nt], a[mt], b[nt >> 1][(nt & 1) * 2],
                                     b[nt >> 1][(nt & 1) * 2 + 1]);
                }
            }

#pragma unroll
            for (int mt = 0; mt < 2; ++mt) {
                int zl = zb + 16 * mt + (lane >> 2);
#pragma unroll
                for (int nt = 0; nt < 4; ++nt) {
                    int c = 32 * wn + 8 * nt + (lane & 3) * 2;
                    if (zl < zv)
                        *(float2*)(out + (size_t)(z0t + zl) * 512 + c) =
                            make_float2(d[mt][nt][0], d[mt][nt][1]);
                    if (zl + 8 < zv)
                        *(float2*)(out + (size_t)(z0t + zl + 8) * 512 + c) =
                            make_float2(d[mt][nt][2], d[mt][nt][3]);
                }
            }
            if (tid == 0) s_t = atomicAdd(&g_tp_ctr[0], 1);
            __syncthreads();
        }
    } else {
        __syncthreads();
        // ---- preload W2 fragments (W2 smem dead afterwards) ----
        uint32_t w2f[8][8];
        {
            const uint32_t wb = sb + OFF_W + 32768;
            const int brow0 = 32 * wn + ((lane >> 4) << 3) + (lane & 7);
            const int bch = (lane >> 3) & 1;
#pragma unroll
            for (int ks = 0; ks < 8; ++ks)
#pragma unroll
                for (int nb = 0; nb < 2; ++nb) {
                    int row = brow0 + 16 * nb;
                    ldsm4(wb + row * 256 + (((ks * 2 + bch) ^ (row & 7)) << 4),
                          &w2f[ks][4 * nb]);
                }
        }
        if (tid == 0) s_t = atomicAdd(&g_tp_ctr[1], 1);
        __syncthreads();

        while (true) {
            const int t = s_t;
            if (t >= NT) break;
            const int z0t = t * TZ;
            const int zv = min(TZ, Z - z0t);

            // ---- FUSED single-loop build: Fa = a/16 AND F0..F2 = s*b_k/16 ----
#pragma unroll 1
            for (int it = 0; it < 4; ++it) {
                int i = tid + it * NTH;
                int z = i >> 4, c = i & 15;
                uint32_t so = (uint32_t)(z * 256 + ((c ^ (z & 7)) << 4));
                if (z < zv) {
                    const float* row = x1 + (size_t)(z0t + z) * 512;
                    const float* ap = row + 8 * c;
                    const float* bp = row + 128 + 24 * c;
                    float4 p0 = *(const float4*)(ap);
                    float4 p1 = *(const float4*)(ap + 4);
                    float arr[24];
#pragma unroll
                    for (int q = 0; q < 6; ++q)
                        *(float4*)(arr + 4 * q) = *(const float4*)(bp + 4 * q);
                    float s = inv16 * __ldg(x2 + (size_t)(z0t + z) * 4);
                    *(uint4*)(smc + OFF_FB + so) =
                        make_uint4(pkh2(inv16 * p0.x, inv16 * p0.y),
                                   pkh2(inv16 * p0.z, inv16 * p0.w),
                                   pkh2(inv16 * p1.x, inv16 * p1.y),
                                   pkh2(inv16 * p1.z, inv16 * p1.w));
#pragma unroll
                    for (int m = 0; m < 24; ++m) arr[m] *= s;
#pragma unroll
                    for (int k = 0; k < 3; ++k)
                        *(uint4*)(smc + OFF_FB + 16384 * (1 + k) + so) =
                            make_uint4(pkh2(arr[k], arr[3 + k]),
                                       pkh2(arr[6 + k], arr[9 + k]),
                                       pkh2(arr[12 + k], arr[15 + k]),
                                       pkh2(arr[18 + k], arr[21 + k]));
                } else {
                    uint4 zz = make_uint4(0, 0, 0, 0);
                    *(uint4*)(smc + OFF_FB + so) = zz;
#pragma unroll
                    for (int k = 0; k < 3; ++k)
                        *(uint4*)(smc + OFF_FB + 16384 * (1 + k) + so) = zz;
                }
            }
            __syncthreads();

            // ---- dt for both z-halves, stash per-thread fp16 ----
#pragma unroll 1
            for (int zh = 0; zh < 2; ++zh) {
                int zbh = 32 * zh + 16 * zm;
                float dt[4][4];
#pragma unroll
                for (int nt = 0; nt < 4; ++nt)
#pragma unroll
                    for (int r = 0; r < 4; ++r) dt[nt][r] = 0.0f;
                gemm16x32<8, 256>(sb + OFF_FB, sb + OFF_W, zbh, wn, lane, dt);
#pragma unroll
                for (int nt = 0; nt < 4; ++nt) {
                    *(uint32_t*)(smc + OFF_ST + (uint32_t)tid * 64 +
                                 (uint32_t)(zh * 32 + nt * 8)) =
                        pkh2(dt[nt][0], dt[nt][1]);
                    *(uint32_t*)(smc + OFF_ST + (uint32_t)tid * 64 +
                                 (uint32_t)(zh * 32 + nt * 8 + 4)) =
                        pkh2(dt[nt][2], dt[nt][3]);
                }
            }

            // ---- du3 per z-half with register-resident W2; contiguous stores ----
#pragma unroll 1
            for (int zh = 0; zh < 2; ++zh) {
                int zbh = 32 * zh + 16 * zm;
                float du3[3][4][4];
#pragma unroll
                for (int k = 0; k < 3; ++k)
#pragma unroll
                    for (int nt = 0; nt < 4; ++nt)
#pragma unroll
                        for (int r = 0; r < 4; ++r) du3[k][nt][r] = 0.0f;
                {
                    const int arow = zbh + (lane & 15);
                    const int ach = lane >> 4;
#pragma unroll
                    for (int ks = 0; ks < 8; ++ks) {
#pragma unroll
                        for (int k = 0; k < 3; ++k) {
                            uint32_t a[4];
                            ldsm4(sb + OFF_FB + 16384 * (1 + k) + arow * 256 +
                                      (((ks * 2 + ach) ^ (arow & 7)) << 4),
                                  a);
#pragma unroll
                            for (int nt = 0; nt < 4; ++nt)
                                mma16816(du3[k][nt], a,
                                         w2f[ks][(nt >> 1) * 4 + (nt & 1) * 2],
                                         w2f[ks][(nt >> 1) * 4 + (nt & 1) * 2 + 1]);
                        }
                    }
                }

                int zl = zbh + (lane >> 2);
                float4 xa = make_float4(0, 0, 0, 0), xb = make_float4(0, 0, 0, 0);
                if (zl < zv)
                    xa = __ldg((const float4*)(x2 + (size_t)(z0t + zl) * 4));
                if (zl + 8 < zv)
                    xb = __ldg((const float4*)(x2 + (size_t)(z0t + zl + 8) * 4));
#pragma unroll
                for (int nt = 0; nt < 4; ++nt) {
                    __half2 hA = *(__half2*)(smc + OFF_ST + (uint32_t)tid * 64 +
                                             (uint32_t)(zh * 32 + nt * 8));
                    __half2 hB = *(__half2*)(smc + OFF_ST + (uint32_t)tid * 64 +
                                             (uint32_t)(zh * 32 + nt * 8 + 4));
                    float t0 = __low2float(hA), t1v = __high2float(hA);
                    float t2 = __low2float(hB), t3 = __high2float(hB);
                    int c = 32 * wn + 8 * nt + (lane & 3) * 2;
                    if (zl < zv) {
                        float* o = out + (size_t)(z0t + zl) * 512 + 128 + 3 * c;
                        *(float2*)(o) =
                            make_float2(fmaf(xa.y, t0, du3[0][nt][0]),
                                        fmaf(xa.z, t0, du3[1][nt][0]));
                        *(float2*)(o + 2) =
                            make_float2(fmaf(xa.w, t0, du3[2][nt][0]),
                                        fmaf(xa.y, t1v, du3[0][nt][1]));
                        *(float2*)(o + 4) =
                            make_float2(fmaf(xa.z, t1v, du3[1][nt][1]),
                                        fmaf(xa.w, t1v, du3[2][nt][1]));
                    }
                    if (zl + 8 < zv) {
                        float* o =
                            out + (size_t)(z0t + zl + 8) * 512 + 128 + 3 * c;
                        *(float2*)(o) =
                            make_float2(fmaf(xb.y, t2, du3[0][nt][2]),
                                        fmaf(xb.z, t2, du3[1][nt][2]));
                        *(float2*)(o + 2) =
                            make_float2(fmaf(xb.w, t2, du3[2][nt][2]),
                                        fmaf(xb.y, t3, du3[0][nt][3]));
                        *(float2*)(o + 4) =
                            make_float2(fmaf(xb.z, t3, du3[1][nt][3]),
                                        fmaf(xb.w, t3, du3[2][nt][3]));
                    }
                }
            }
            if (tid == 0) s_t = atomicAdd(&g_tp_ctr[1], 1);
            __syncthreads();
        }
    }
}

extern "C" void kernel_launch(void* const* d_in, const int* in_sizes, int n_in,
                              void* d_out, int out_size) {
    const float* x1 = (const float*)d_in[0];
    const float* x2 = (const float*)d_in[1];
    const float* w = (const float*)d_in[2];
    float* out = (float*)d_out;
    const int Z = in_sizes[0] / 512;
    const int NT = (Z + TZ - 1) / TZ;

    int dev = 0;
    cudaGetDevice(&dev);
    int sms = 148;
    cudaDeviceGetAttribute(&sms, cudaDevAttrMultiProcessorCount, dev);

    cudaFuncSetAttribute(tp_hmma12, cudaFuncAttributeMaxDynamicSharedMemorySize,
                         SMEM_BYTES);
    int grid = 2 * sms;
    if (grid > NT) grid = NT;
    int NA = (grid * 40) / 100;
    if (NA < 1) NA = 1;
    if (NA > grid - 1) NA = grid - 1;
    int NB = grid - NA;

    tp_init_ctr<<<1, 32>>>();
    tp_hmma12<<<grid, NTH, SMEM_BYTES>>>(x1, x2, w, out, Z, NT, NA, NB);
}

// round 15
// speedup vs baseline: 1.0042x; 1.0042x over previous
#include <cuda_runtime.h>
#include <cuda_fp16.h>
#include <cstdint>

#define NTH 256
#define TZ 64

#define OFF_W 0
#define OFF_FA 65536
#define OFF_FB 32768
#define OFF_ST 98304
#define SMEM_BYTES 114688

static __device__ __forceinline__ uint32_t s2u(const void* p) {
    uint32_t a;
    asm("{ .reg .u64 t; cvta.to.shared.u64 t, %1; cvt.u32.u64 %0, t; }"
        : "=r"(a) : "l"(p));
    return a;
}

static __device__ __forceinline__ uint32_t pkh2(float a, float b) {
    __half2 h = __floats2half2_rn(a, b);
    return *reinterpret_cast<uint32_t*>(&h);
}

static __device__ __forceinline__ void ldsm4(uint32_t addr, uint32_t r[4]) {
    asm volatile("ldmatrix.sync.aligned.m8n8.x4.shared.b16 {%0,%1,%2,%3}, [%4];"
                 : "=r"(r[0]), "=r"(r[1]), "=r"(r[2]), "=r"(r[3])
                 : "r"(addr));
}

static __device__ __forceinline__ void mma16816(float d[4], const uint32_t a[4],
                                                uint32_t b0, uint32_t b1) {
    asm volatile(
        "mma.sync.aligned.m16n8k16.row.col.f32.f16.f16.f32 "
        "{%0,%1,%2,%3}, {%4,%5,%6,%7}, {%8,%9}, {%0,%1,%2,%3};"
        : "+f"(d[0]), "+f"(d[1]), "+f"(d[2]), "+f"(d[3])
        : "r"(a[0]), "r"(a[1]), "r"(a[2]), "r"(a[3]), "r"(b0), "r"(b1));
}

__global__ void __launch_bounds__(NTH, 2)
tp_hmma13(const float* __restrict__ x1, const float* __restrict__ x2,
          const float* __restrict__ wts, float* __restrict__ out,
          int Z, int NT, int NA, int NB) {
    extern __shared__ char smc[];
    const uint32_t sb = s2u(smc);
    const int tid = threadIdx.x;
    const int lane = tid & 31, wid = tid >> 5;
    const int zm = wid & 1, wn = wid >> 1;
    const bool roleA = (int)blockIdx.x < NA;
    const float inv16 = 0.0625f;
    const float c2 = 0.03608439182435161f;  // 1/(16*sqrt(3))

    // ---- weights into smem (fp16, [w][k], swizzled) ----
    if (roleA) {
        for (int i = tid; i < 4096; i += NTH) {
            int w = i >> 5, c = i & 31;
            const float* src = (c < 16) ? wts : (wts + 49152);  // W0 / W3
            int u0 = (c & 15) * 8;
            uint32_t h[4];
#pragma unroll
            for (int j = 0; j < 4; ++j)
                h[j] = pkh2(src[(u0 + 2 * j) * 128 + w],
                            src[(u0 + 2 * j + 1) * 128 + w]);
            *(uint4*)(smc + OFF_W + w * 512 + ((c ^ (w & 7)) << 4)) =
                make_uint4(h[0], h[1], h[2], h[3]);
        }
    } else {
        for (int i = tid; i < 2048; i += NTH) {
            int w = i >> 4, c = i & 15;
            int u0 = c * 8;
            const float* s1 = wts + 16384;  // W1
            const float* s2 = wts + 32768;  // W2
            uint32_t h1[4], h2[4];
#pragma unroll
            for (int j = 0; j < 4; ++j) {
                h1[j] = pkh2(s1[(u0 + 2 * j) * 128 + w],
                             s1[(u0 + 2 * j + 1) * 128 + w]);
                h2[j] = pkh2(s2[(u0 + 2 * j) * 128 + w],
                             s2[(u0 + 2 * j + 1) * 128 + w]);
            }
            uint32_t so = (uint32_t)(w * 256 + ((c ^ (w & 7)) << 4));
            *(uint4*)(smc + OFF_W + so) = make_uint4(h1[0], h1[1], h1[2], h1[3]);
            *(uint4*)(smc + OFF_W + 32768 + so) =
                make_uint4(h2[0], h2[1], h2[2], h2[3]);
        }
    }
    __syncthreads();

    if (roleA) {
        // ---- preload W0-half B fragments into registers ----
        uint32_t w0f[8][8];
        {
            const int brow0 = 32 * wn + ((lane >> 4) << 3) + (lane & 7);
            const int bch = (lane >> 3) & 1;
#pragma unroll
            for (int ks = 0; ks < 8; ++ks)
#pragma unroll
                for (int nb = 0; nb < 2; ++nb) {
                    int row = brow0 + 16 * nb;
                    ldsm4(sb + OFF_W + row * 512 +
                              (((ks * 2 + bch) ^ (row & 7)) << 4),
                          &w0f[ks][4 * nb]);
                }
        }
        const int zb = 32 * zm;
        for (int t = (int)blockIdx.x; t < NT; t += NA) {
            const int z0t = t * TZ;
            const int zv = min(TZ, Z - z0t);

            // a-part: k chunks 0..15 (non-divergent)
#pragma unroll 2
            for (int it = 0; it < 4; ++it) {
                int i = tid + it * NTH;
                int z = i >> 4, c = i & 15;
                uint4 wv = make_uint4(0, 0, 0, 0);
                if (z < zv) {
                    float s = inv16 * __ldg(x2 + (size_t)(z0t + z) * 4);
                    const float* ap = x1 + (size_t)(z0t + z) * 512 + 8 * c;
                    float4 p0 = *(const float4*)(ap);
                    float4 p1 = *(const float4*)(ap + 4);
                    wv = make_uint4(pkh2(s * p0.x, s * p0.y),
                                    pkh2(s * p0.z, s * p0.w),
                                    pkh2(s * p1.x, s * p1.y),
                                    pkh2(s * p1.z, s * p1.w));
                }
                *(uint4*)(smc + OFF_FA + z * 512 + ((c ^ (z & 7)) << 4)) = wv;
            }
            // b-part: k chunks 16..31 (non-divergent)
#pragma unroll 1
            for (int it = 0; it < 4; ++it) {
                int i = tid + it * NTH;
                int z = i >> 4, c = (i & 15) + 16;
                uint4 wv = make_uint4(0, 0, 0, 0);
                if (z < zv) {
                    float4 xv = __ldg((const float4*)(x2 + (size_t)(z0t + z) * 4));
                    const float* bp =
                        x1 + (size_t)(z0t + z) * 512 + 128 + 24 * (c - 16);
                    float arr[24];
#pragma unroll
                    for (int q = 0; q < 6; ++q)
                        *(float4*)(arr + 4 * q) = *(const float4*)(bp + 4 * q);
                    float f[8];
#pragma unroll
                    for (int j = 0; j < 8; ++j)
                        f[j] = c2 * (arr[3 * j] * xv.y + arr[3 * j + 1] * xv.z +
                                     arr[3 * j + 2] * xv.w);
                    wv = make_uint4(pkh2(f[0], f[1]), pkh2(f[2], f[3]),
                                    pkh2(f[4], f[5]), pkh2(f[6], f[7]));
                }
                *(uint4*)(smc + OFF_FA + z * 512 + ((c ^ (z & 7)) << 4)) = wv;
            }
            __syncthreads();

            float d[2][4][4];
#pragma unroll
            for (int mt = 0; mt < 2; ++mt)
#pragma unroll
                for (int nt = 0; nt < 4; ++nt)
#pragma unroll
                    for (int r = 0; r < 4; ++r) d[mt][nt][r] = 0.0f;
            {
                const int arow0 = zb + (lane & 15);
                const int ach = lane >> 4;
                const int brow0 = 32 * wn + ((lane >> 4) << 3) + (lane & 7);
                const int bch = (lane >> 3) & 1;
#pragma unroll
                for (int ks = 0; ks < 8; ++ks) {
                    uint32_t a[2][4];
#pragma unroll
                    for (int mt = 0; mt < 2; ++mt) {
                        int row = arow0 + 16 * mt;
                        ldsm4(sb + OFF_FA + row * 512 +
                                  (((ks * 2 + ach) ^ (row & 7)) << 4),
                              a[mt]);
                    }
#pragma unroll
                    for (int mt = 0; mt < 2; ++mt)
#pragma unroll
                        for (int nt = 0; nt < 4; ++nt)
                            mma16816(d[mt][nt], a[mt],
                                     w0f[ks][(nt >> 1) * 4 + (nt & 1) * 2],
                                     w0f[ks][(nt >> 1) * 4 + (nt & 1) * 2 + 1]);
                }
#pragma unroll
                for (int ks = 8; ks < 16; ++ks) {
                    uint32_t a[2][4];
#pragma unroll
                    for (int mt = 0; mt < 2; ++mt) {
                        int row = arow0 + 16 * mt;
                        ldsm4(sb + OFF_FA + row * 512 +
                                  (((ks * 2 + ach) ^ (row & 7)) << 4),
                              a[mt]);
                    }
                    uint32_t b[2][4];
#pragma unroll
                    for (int nb = 0; nb < 2; ++nb) {
                        int row = brow0 + 16 * nb;
                        ldsm4(sb + OFF_W + row * 512 +
                                  (((ks * 2 + bch) ^ (row & 7)) << 4),
                              b[nb]);
                    }
#pragma unroll
                    for (int mt = 0; mt < 2; ++mt)
#pragma unroll
                        for (int nt = 0; nt < 4; ++nt)
                            mma16816(d[mt][nt], a[mt], b[nt >> 1][(nt & 1) * 2],
                                     b[nt >> 1][(nt & 1) * 2 + 1]);
                }
            }

#pragma unroll
            for (int mt = 0; mt < 2; ++mt) {
                int zl = zb + 16 * mt + (lane >> 2);
#pragma unroll
                for (int nt = 0; nt < 4; ++nt) {
                    int c = 32 * wn + 8 * nt + (lane & 3) * 2;
                    if (zl < zv)
                        *(float2*)(out + (size_t)(z0t + zl) * 512 + c) =
                            make_float2(d[mt][nt][0], d[mt][nt][1]);
                    if (zl + 8 < zv)
                        *(float2*)(out + (size_t)(z0t + zl + 8) * 512 + c) =
                            make_float2(d[mt][nt][2], d[mt][nt][3]);
                }
            }
            __syncthreads();
        }
    } else {
        // ---- preload W2 fragments (W2 smem dead afterwards) ----
        uint32_t w2f[8][8];
        {
            const uint32_t wb = sb + OFF_W + 32768;
            const int brow0 = 32 * wn + ((lane >> 4) << 3) + (lane & 7);
            const int bch = (lane >> 3) & 1;
#pragma unroll
            for (int ks = 0; ks < 8; ++ks)
#pragma unroll
                for (int nb = 0; nb < 2; ++nb) {
                    int row = brow0 + 16 * nb;
                    ldsm4(wb + row * 256 + (((ks * 2 + bch) ^ (row & 7)) << 4),
                          &w2f[ks][4 * nb]);
                }
        }
        __syncthreads();

        for (int t = (int)blockIdx.x - NA; t < NT; t += NB) {
            const int z0t = t * TZ;
            const int zv = min(TZ, Z - z0t);

            // ---- FUSED single-loop build: Fa = a/16 AND F0..F2 = s*b_k/16 ----
#pragma unroll 1
            for (int it = 0; it < 4; ++it) {
                int i = tid + it * NTH;
                int z = i >> 4, c = i & 15;
                uint32_t so = (uint32_t)(z * 256 + ((c ^ (z & 7)) << 4));
                if (z < zv) {
                    const float* row = x1 + (size_t)(z0t + z) * 512;
                    const float* ap = row + 8 * c;
                    const float* bp = row + 128 + 24 * c;
                    float4 p0 = *(const float4*)(ap);
                    float4 p1 = *(const float4*)(ap + 4);
                    float arr[24];
#pragma unroll
                    for (int q = 0; q < 6; ++q)
                        *(float4*)(arr + 4 * q) = *(const float4*)(bp + 4 * q);
                    float s = inv16 * __ldg(x2 + (size_t)(z0t + z) * 4);
                    *(uint4*)(smc + OFF_FB + so) =
                        make_uint4(pkh2(inv16 * p0.x, inv16 * p0.y),
                                   pkh2(inv16 * p0.z, inv16 * p0.w),
                                   pkh2(inv16 * p1.x, inv16 * p1.y),
                                   pkh2(inv16 * p1.z, inv16 * p1.w));
#pragma unroll
                    for (int m = 0; m < 24; ++m) arr[m] *= s;
#pragma unroll
                    for (int k = 0; k < 3; ++k)
                        *(uint4*)(smc + OFF_FB + 16384 * (1 + k) + so) =
                            make_uint4(pkh2(arr[k], arr[3 + k]),
                                       pkh2(arr[6 + k], arr[9 + k]),
                                       pkh2(arr[12 + k], arr[15 + k]),
                                       pkh2(arr[18 + k], arr[21 + k]));
                } else {
                    uint4 zz = make_uint4(0, 0, 0, 0);
                    *(uint4*)(smc + OFF_FB + so) = zz;
#pragma unroll
                    for (int k = 0; k < 3; ++k)
                        *(uint4*)(smc + OFF_FB + 16384 * (1 + k) + so) = zz;
                }
            }
            __syncthreads();

            // ---- dt for both z-halves, FUSED ks loop (W1 B-frags read ONCE) ----
            {
                float dt[2][4][4];
#pragma unroll
                for (int zh = 0; zh < 2; ++zh)
#pragma unroll
                    for (int nt = 0; nt < 4; ++nt)
#pragma unroll
                        for (int r = 0; r < 4; ++r) dt[zh][nt][r] = 0.0f;
                const int ach = lane >> 4;
                const int brow0 = 32 * wn + ((lane >> 4) << 3) + (lane & 7);
                const int bch = (lane >> 3) & 1;
#pragma unroll
                for (int ks = 0; ks < 8; ++ks) {
                    uint32_t b[2][4];
#pragma unroll
                    for (int nb = 0; nb < 2; ++nb) {
                        int row = brow0 + 16 * nb;
                        ldsm4(sb + OFF_W + row * 256 +
                                  (((ks * 2 + bch) ^ (row & 7)) << 4),
                              b[nb]);
                    }
#pragma unroll
                    for (int zh = 0; zh < 2; ++zh) {
                        int arow = 32 * zh + 16 * zm + (lane & 15);
                        uint32_t a[4];
                        ldsm4(sb + OFF_FB + arow * 256 +
                                  (((ks * 2 + ach) ^ (arow & 7)) << 4),
                              a);
#pragma unroll
                        for (int nt = 0; nt < 4; ++nt)
                            mma16816(dt[zh][nt], a, b[nt >> 1][(nt & 1) * 2],
                                     b[nt >> 1][(nt & 1) * 2 + 1]);
                    }
                }
                // stash per-thread fp16 (same layout as R13)
#pragma unroll
                for (int zh = 0; zh < 2; ++zh)
#pragma unroll
                    for (int nt = 0; nt < 4; ++nt) {
                        *(uint32_t*)(smc + OFF_ST + (uint32_t)tid * 64 +
                                     (uint32_t)(zh * 32 + nt * 8)) =
                            pkh2(dt[zh][nt][0], dt[zh][nt][1]);
                        *(uint32_t*)(smc + OFF_ST + (uint32_t)tid * 64 +
                                     (uint32_t)(zh * 32 + nt * 8 + 4)) =
                            pkh2(dt[zh][nt][2], dt[zh][nt][3]);
                    }
            }

            // ---- du3 per z-half with register-resident W2; contiguous stores ----
#pragma unroll 1
            for (int zh = 0; zh < 2; ++zh) {
                int zbh = 32 * zh + 16 * zm;
                float du3[3][4][4];
#pragma unroll
                for (int k = 0; k < 3; ++k)
#pragma unroll
                    for (int nt = 0; nt < 4; ++nt)
#pragma unroll
                        for (int r = 0; r < 4; ++r) du3[k][nt][r] = 0.0f;
                {
                    const int arow = zbh + (lane & 15);
                    const int ach = lane >> 4;
#pragma unroll
                    for (int ks = 0; ks < 8; ++ks) {
#pragma unroll
                        for (int k = 0; k < 3; ++k) {
                            uint32_t a[4];
                            ldsm4(sb + OFF_FB + 16384 * (1 + k) + arow * 256 +
                                      (((ks * 2 + ach) ^ (arow & 7)) << 4),
                                  a);
#pragma unroll
                            for (int nt = 0; nt < 4; ++nt)
                                mma16816(du3[k][nt], a,
                                         w2f[ks][(nt >> 1) * 4 + (nt & 1) * 2],
                                         w2f[ks][(nt >> 1) * 4 + (nt & 1) * 2 + 1]);
                        }
                    }
                }

                int zl = zbh + (lane >> 2);
                float4 xa = make_float4(0, 0, 0, 0), xb = make_float4(0, 0, 0, 0);
                if (zl < zv)
                    xa = __ldg((const float4*)(x2 + (size_t)(z0t + zl) * 4));
                if (zl + 8 < zv)
                    xb = __ldg((const float4*)(x2 + (size_t)(z0t + zl + 8) * 4));
#pragma unroll
                for (int nt = 0; nt < 4; ++nt) {
                    __half2 hA = *(__half2*)(smc + OFF_ST + (uint32_t)tid * 64 +
                                             (uint32_t)(zh * 32 + nt * 8));
                    __half2 hB = *(__half2*)(smc + OFF_ST + (uint32_t)tid * 64 +
                                             (uint32_t)(zh * 32 + nt * 8 + 4));
                    float t0 = __low2float(hA), t1v = __high2float(hA);
                    float t2 = __low2float(hB), t3 = __high2float(hB);
                    int c = 32 * wn + 8 * nt + (lane & 3) * 2;
                    if (zl < zv) {
                        float* o = out + (size_t)(z0t + zl) * 512 + 128 + 3 * c;
                        *(float2*)(o) =
                            make_float2(fmaf(xa.y, t0, du3[0][nt][0]),
                                        fmaf(xa.z, t0, du3[1][nt][0]));
                        *(float2*)(o + 2) =
                            make_float2(fmaf(xa.w, t0, du3[2][nt][0]),
                                        fmaf(xa.y, t1v, du3[0][nt][1]));
                        *(float2*)(o + 4) =
                            make_float2(fmaf(xa.z, t1v, du3[1][nt][1]),
                                        fmaf(xa.w, t1v, du3[2][nt][1]));
                    }
                    if (zl + 8 < zv) {
                        float* o =
                            out + (size_t)(z0t + zl + 8) * 512 + 128 + 3 * c;
                        *(float2*)(o) =
                            make_float2(fmaf(xb.y, t2, du3[0][nt][2]),
                                        fmaf(xb.z, t2, du3[1][nt][2]));
                        *(float2*)(o + 2) =
                            make_float2(fmaf(xb.w, t2, du3[2][nt][2]),
                                        fmaf(xb.y, t3, du3[0][nt][3]));
                        *(float2*)(o + 4) =
                            make_float2(fmaf(xb.z, t3, du3[1][nt][3]),
                                        fmaf(xb.w, t3, du3[2][nt][3]));
                    }
                }
            }
            __syncthreads();
        }
    }
}

extern "C" void kernel_launch(void* const* d_in, const int* in_sizes, int n_in,
                              void* d_out, int out_size) {
    const float* x1 = (const float*)d_in[0];
    const float* x2 = (const float*)d_in[1];
    const float* w = (const float*)d_in[2];
    float* out = (float*)d_out;
    const int Z = in_sizes[0] / 512;
    const int NT = (Z + TZ - 1) / TZ;

    int dev = 0;
    cudaGetDevice(&dev);
    int sms = 148;
    cudaDeviceGetAttribute(&sms, cudaDevAttrMultiProcessorCount, dev);

    cudaFuncSetAttribute(tp_hmma13, cudaFuncAttributeMaxDynamicSharedMemorySize,
                         SMEM_BYTES);
    int grid = 2 * sms;
    if (grid > NT) grid = NT;
    int NA = (grid * 38) / 100;
    if (NA < 1) NA = 1;
    if (NA > grid - 1) NA = grid - 1;
    int NB = grid - NA;

    tp_hmma13<<<grid, NTH, SMEM_BYTES>>>(x1, x2, w, out, Z, NT, NA, NB);
}

// round 16
// speedup vs baseline: 1.0317x; 1.0274x over previous
#include <cuda_runtime.h>
#include <cuda_fp16.h>
#include <cstdint>

#define NTH 256
#define TZ 64

#define OFF_W 0
#define OFF_FA 65536
#define OFF_FB 32768
#define OFF_ST 98304
#define SMEM_BYTES 114688

static __device__ __forceinline__ uint32_t s2u(const void* p) {
    uint32_t a;
    asm("{ .reg .u64 t; cvta.to.shared.u64 t, %1; cvt.u32.u64 %0, t; }"
        : "=r"(a) : "l"(p));
    return a;
}

static __device__ __forceinline__ uint32_t pkh2(float a, float b) {
    __half2 h = __floats2half2_rn(a, b);
    return *reinterpret_cast<uint32_t*>(&h);
}

static __device__ __forceinline__ void ldsm4(uint32_t addr, uint32_t r[4]) {
    asm volatile("ldmatrix.sync.aligned.m8n8.x4.shared.b16 {%0,%1,%2,%3}, [%4];"
                 : "=r"(r[0]), "=r"(r[1]), "=r"(r[2]), "=r"(r[3])
                 : "r"(addr));
}

static __device__ __forceinline__ void mma16816(float d[4], const uint32_t a[4],
                                                uint32_t b0, uint32_t b1) {
    asm volatile(
        "mma.sync.aligned.m16n8k16.row.col.f32.f16.f16.f32 "
        "{%0,%1,%2,%3}, {%4,%5,%6,%7}, {%8,%9}, {%0,%1,%2,%3};"
        : "+f"(d[0]), "+f"(d[1]), "+f"(d[2]), "+f"(d[3])
        : "r"(a[0]), "r"(a[1]), "r"(a[2]), "r"(a[3]), "r"(b0), "r"(b1));
}

// role B: warp tile 16z x 32w via ldmatrix both operands
template <int NKS, int RB>
static __device__ __forceinline__ void gemm16x32(uint32_t fbase, uint32_t wbase,
                                                 int zb, int wn, int lane,
                                                 float d[4][4]) {
    const int arow = zb + (lane & 15);
    const int ach = lane >> 4;
    const int brow0 = 32 * wn + ((lane >> 4) << 3) + (lane & 7);
    const int bch = (lane >> 3) & 1;
#pragma unroll
    for (int ks = 0; ks < NKS; ++ks) {
        uint32_t a[4];
        ldsm4(fbase + arow * RB + (((ks * 2 + ach) ^ (arow & 7)) << 4), a);
        uint32_t b[2][4];
#pragma unroll
        for (int nb = 0; nb < 2; ++nb) {
            int row = brow0 + 16 * nb;
            ldsm4(wbase + row * RB + (((ks * 2 + bch) ^ (row & 7)) << 4), b[nb]);
        }
#pragma unroll
        for (int nt = 0; nt < 4; ++nt)
            mma16816(d[nt], a, b[nt >> 1][(nt & 1) * 2],
                     b[nt >> 1][(nt & 1) * 2 + 1]);
    }
}

__global__ void __launch_bounds__(NTH, 2)
tp_hmma14(const float* __restrict__ x1, const float* __restrict__ x2,
          const float* __restrict__ wts, float* __restrict__ out,
          int Z, int NT, int NA, int NB) {
    extern __shared__ char smc[];
    const uint32_t sb = s2u(smc);
    const int tid = threadIdx.x;
    const int lane = tid & 31, wid = tid >> 5;
    const int zm = wid & 1, wn = wid >> 1;
    const bool roleA = (int)blockIdx.x < NA;
    const float inv16 = 0.0625f;
    const float c2 = 0.03608439182435161f;  // 1/(16*sqrt(3))

    // ---- weights into smem (fp16, [w][k], swizzled), SCALES FOLDED IN ----
    if (roleA) {
        for (int i = tid; i < 4096; i += NTH) {
            int w = i >> 5, c = i & 31;
            const float* src = (c < 16) ? wts : (wts + 49152);  // W0 / W3
            const float sc = (c < 16) ? inv16 : c2;
            int u0 = (c & 15) * 8;
            uint32_t h[4];
#pragma unroll
            for (int j = 0; j < 4; ++j)
                h[j] = pkh2(sc * src[(u0 + 2 * j) * 128 + w],
                            sc * src[(u0 + 2 * j + 1) * 128 + w]);
            *(uint4*)(smc + OFF_W + w * 512 + ((c ^ (w & 7)) << 4)) =
                make_uint4(h[0], h[1], h[2], h[3]);
        }
    } else {
        for (int i = tid; i < 2048; i += NTH) {
            int w = i >> 4, c = i & 15;
            int u0 = c * 8;
            const float* s1 = wts + 16384;  // W1
            const float* s2 = wts + 32768;  // W2
            uint32_t h1[4], h2[4];
#pragma unroll
            for (int j = 0; j < 4; ++j) {
                h1[j] = pkh2(inv16 * s1[(u0 + 2 * j) * 128 + w],
                             inv16 * s1[(u0 + 2 * j + 1) * 128 + w]);
                h2[j] = pkh2(inv16 * s2[(u0 + 2 * j) * 128 + w],
                             inv16 * s2[(u0 + 2 * j + 1) * 128 + w]);
            }
            uint32_t so = (uint32_t)(w * 256 + ((c ^ (w & 7)) << 4));
            *(uint4*)(smc + OFF_W + so) = make_uint4(h1[0], h1[1], h1[2], h1[3]);
            *(uint4*)(smc + OFF_W + 32768 + so) =
                make_uint4(h2[0], h2[1], h2[2], h2[3]);
        }
    }
    __syncthreads();

    if (roleA) {
        // ---- preload W0-half B fragments into registers ----
        uint32_t w0f[8][8];
        {
            const int brow0 = 32 * wn + ((lane >> 4) << 3) + (lane & 7);
            const int bch = (lane >> 3) & 1;
#pragma unroll
            for (int ks = 0; ks < 8; ++ks)
#pragma unroll
                for (int nb = 0; nb < 2; ++nb) {
                    int row = brow0 + 16 * nb;
                    ldsm4(sb + OFF_W + row * 512 +
                              (((ks * 2 + bch) ^ (row & 7)) << 4),
                          &w0f[ks][4 * nb]);
                }
        }
        const int zb = 32 * zm;
        for (int t = (int)blockIdx.x; t < NT; t += NA) {
            const int z0t = t * TZ;
            const int zv = min(TZ, Z - z0t);

            // a-part: k chunks 0..15 (f = x2.x * a; inv16 folded into W0)
#pragma unroll 2
            for (int it = 0; it < 4; ++it) {
                int i = tid + it * NTH;
                int z = i >> 4, c = i & 15;
                uint4 wv = make_uint4(0, 0, 0, 0);
                if (z < zv) {
                    float s = __ldg(x2 + (size_t)(z0t + z) * 4);
                    const float* ap = x1 + (size_t)(z0t + z) * 512 + 8 * c;
                    float4 p0 = *(const float4*)(ap);
                    float4 p1 = *(const float4*)(ap + 4);
                    wv = make_uint4(pkh2(s * p0.x, s * p0.y),
                                    pkh2(s * p0.z, s * p0.w),
                                    pkh2(s * p1.x, s * p1.y),
                                    pkh2(s * p1.z, s * p1.w));
                }
                *(uint4*)(smc + OFF_FA + z * 512 + ((c ^ (z & 7)) << 4)) = wv;
            }
            // b-part: k chunks 16..31 (f = B.v; c2 folded into W3)
#pragma unroll 1
            for (int it = 0; it < 4; ++it) {
                int i = tid + it * NTH;
                int z = i >> 4, c = (i & 15) + 16;
                uint4 wv = make_uint4(0, 0, 0, 0);
                if (z < zv) {
                    float4 xv = __ldg((const float4*)(x2 + (size_t)(z0t + z) * 4));
                    const float* bp =
                        x1 + (size_t)(z0t + z) * 512 + 128 + 24 * (c - 16);
                    float arr[24];
#pragma unroll
                    for (int q = 0; q < 6; ++q)
                        *(float4*)(arr + 4 * q) = *(const float4*)(bp + 4 * q);
                    float f[8];
#pragma unroll
                    for (int j = 0; j < 8; ++j)
                        f[j] = arr[3 * j] * xv.y + arr[3 * j + 1] * xv.z +
                               arr[3 * j + 2] * xv.w;
                    wv = make_uint4(pkh2(f[0], f[1]), pkh2(f[2], f[3]),
                                    pkh2(f[4], f[5]), pkh2(f[6], f[7]));
                }
                *(uint4*)(smc + OFF_FA + z * 512 + ((c ^ (z & 7)) << 4)) = wv;
            }
            __syncthreads();

            float d[2][4][4];
#pragma unroll
            for (int mt = 0; mt < 2; ++mt)
#pragma unroll
                for (int nt = 0; nt < 4; ++nt)
#pragma unroll
                    for (int r = 0; r < 4; ++r) d[mt][nt][r] = 0.0f;
            {
                const int arow0 = zb + (lane & 15);
                const int ach = lane >> 4;
                const int brow0 = 32 * wn + ((lane >> 4) << 3) + (lane & 7);
                const int bch = (lane >> 3) & 1;
#pragma unroll
                for (int ks = 0; ks < 8; ++ks) {
                    uint32_t a[2][4];
#pragma unroll
                    for (int mt = 0; mt < 2; ++mt) {
                        int row = arow0 + 16 * mt;
                        ldsm4(sb + OFF_FA + row * 512 +
                                  (((ks * 2 + ach) ^ (row & 7)) << 4),
                              a[mt]);
                    }
#pragma unroll
                    for (int mt = 0; mt < 2; ++mt)
#pragma unroll
                        for (int nt = 0; nt < 4; ++nt)
                            mma16816(d[mt][nt], a[mt],
                                     w0f[ks][(nt >> 1) * 4 + (nt & 1) * 2],
                                     w0f[ks][(nt >> 1) * 4 + (nt & 1) * 2 + 1]);
                }
#pragma unroll
                for (int ks = 8; ks < 16; ++ks) {
                    uint32_t a[2][4];
#pragma unroll
                    for (int mt = 0; mt < 2; ++mt) {
                        int row = arow0 + 16 * mt;
                        ldsm4(sb + OFF_FA + row * 512 +
                                  (((ks * 2 + ach) ^ (row & 7)) << 4),
                              a[mt]);
                    }
                    uint32_t b[2][4];
#pragma unroll
                    for (int nb = 0; nb < 2; ++nb) {
                        int row = brow0 + 16 * nb;
                        ldsm4(sb + OFF_W + row * 512 +
                                  (((ks * 2 + bch) ^ (row & 7)) << 4),
                              b[nb]);
                    }
#pragma unroll
                    for (int mt = 0; mt < 2; ++mt)
#pragma unroll
                        for (int nt = 0; nt < 4; ++nt)
                            mma16816(d[mt][nt], a[mt], b[nt >> 1][(nt & 1) * 2],
                                     b[nt >> 1][(nt & 1) * 2 + 1]);
                }
            }

#pragma unroll
            for (int mt = 0; mt < 2; ++mt) {
                int zl = zb + 16 * mt + (lane >> 2);
#pragma unroll
                for (int nt = 0; nt < 4; ++nt) {
                    int c = 32 * wn + 8 * nt + (lane & 3) * 2;
                    if (zl < zv)
                        *(float2*)(out + (size_t)(z0t + zl) * 512 + c) =
                            make_float2(d[mt][nt][0], d[mt][nt][1]);
                    if (zl + 8 < zv)
                        *(float2*)(out + (size_t)(z0t + zl + 8) * 512 + c) =
                            make_float2(d[mt][nt][2], d[mt][nt][3]);
                }
            }
            __syncthreads();
        }
    } else {
        // ---- preload W2 fragments (W2 smem dead afterwards) ----
        uint32_t w2f[8][8];
        {
            const uint32_t wb = sb + OFF_W + 32768;
            const int brow0 = 32 * wn + ((lane >> 4) << 3) + (lane & 7);
            const int bch = (lane >> 3) & 1;
#pragma unroll
            for (int ks = 0; ks < 8; ++ks)
#pragma unroll
                for (int nb = 0; nb < 2; ++nb) {
                    int row = brow0 + 16 * nb;
                    ldsm4(wb + row * 256 + (((ks * 2 + bch) ^ (row & 7)) << 4),
                          &w2f[ks][4 * nb]);
                }
        }
        __syncthreads();

        for (int t = (int)blockIdx.x - NA; t < NT; t += NB) {
            const int z0t = t * TZ;
            const int zv = min(TZ, Z - z0t);

            // ---- FUSED build: Fa = raw a (inv16 in W1); F_k = x2.x * b_k ----
#pragma unroll 1
            for (int it = 0; it < 4; ++it) {
                int i = tid + it * NTH;
                int z = i >> 4, c = i & 15;
                uint32_t so = (uint32_t)(z * 256 + ((c ^ (z & 7)) << 4));
                if (z < zv) {
                    const float* row = x1 + (size_t)(z0t + z) * 512;
                    const float* ap = row + 8 * c;
                    const float* bp = row + 128 + 24 * c;
                    float4 p0 = *(const float4*)(ap);
                    float4 p1 = *(const float4*)(ap + 4);
                    float arr[24];
#pragma unroll
                    for (int q = 0; q < 6; ++q)
                        *(float4*)(arr + 4 * q) = *(const float4*)(bp + 4 * q);
                    float s = __ldg(x2 + (size_t)(z0t + z) * 4);
                    *(uint4*)(smc + OFF_FB + so) =
                        make_uint4(pkh2(p0.x, p0.y), pkh2(p0.z, p0.w),
                                   pkh2(p1.x, p1.y), pkh2(p1.z, p1.w));
#pragma unroll
                    for (int m = 0; m < 24; ++m) arr[m] *= s;
#pragma unroll
                    for (int k = 0; k < 3; ++k)
                        *(uint4*)(smc + OFF_FB + 16384 * (1 + k) + so) =
                            make_uint4(pkh2(arr[k], arr[3 + k]),
                                       pkh2(arr[6 + k], arr[9 + k]),
                                       pkh2(arr[12 + k], arr[15 + k]),
                                       pkh2(arr[18 + k], arr[21 + k]));
                } else {
                    uint4 zz = make_uint4(0, 0, 0, 0);
                    *(uint4*)(smc + OFF_FB + so) = zz;
#pragma unroll
                    for (int k = 0; k < 3; ++k)
                        *(uint4*)(smc + OFF_FB + 16384 * (1 + k) + so) = zz;
                }
            }
            __syncthreads();

            // ---- dt for both z-halves, stash per-thread fp16 ----
#pragma unroll 1
            for (int zh = 0; zh < 2; ++zh) {
                int zbh = 32 * zh + 16 * zm;
                float dt[4][4];
#pragma unroll
                for (int nt = 0; nt < 4; ++nt)
#pragma unroll
                    for (int r = 0; r < 4; ++r) dt[nt][r] = 0.0f;
                gemm16x32<8, 256>(sb + OFF_FB, sb + OFF_W, zbh, wn, lane, dt);
#pragma unroll
                for (int nt = 0; nt < 4; ++nt) {
                    *(uint32_t*)(smc + OFF_ST + (uint32_t)tid * 64 +
                                 (uint32_t)(zh * 32 + nt * 8)) =
                        pkh2(dt[nt][0], dt[nt][1]);
                    *(uint32_t*)(smc + OFF_ST + (uint32_t)tid * 64 +
                                 (uint32_t)(zh * 32 + nt * 8 + 4)) =
                        pkh2(dt[nt][2], dt[nt][3]);
                }
            }

            // ---- du3 per z-half with register-resident W2; contiguous stores ----
#pragma unroll 1
            for (int zh = 0; zh < 2; ++zh) {
                int zbh = 32 * zh + 16 * zm;
                float du3[3][4][4];
#pragma unroll
                for (int k = 0; k < 3; ++k)
#pragma unroll
                    for (int nt = 0; nt < 4; ++nt)
#pragma unroll
                        for (int r = 0; r < 4; ++r) du3[k][nt][r] = 0.0f;
                {
                    const int arow = zbh + (lane & 15);
                    const int ach = lane >> 4;
#pragma unroll
                    for (int ks = 0; ks < 8; ++ks) {
#pragma unroll
                        for (int k = 0; k < 3; ++k) {
                            uint32_t a[4];
                            ldsm4(sb + OFF_FB + 16384 * (1 + k) + arow * 256 +
                                      (((ks * 2 + ach) ^ (arow & 7)) << 4),
                                  a);
#pragma unroll
                            for (int nt = 0; nt < 4; ++nt)
                                mma16816(du3[k][nt], a,
                                         w2f[ks][(nt >> 1) * 4 + (nt & 1) * 2],
                                         w2f[ks][(nt >> 1) * 4 + (nt & 1) * 2 + 1]);
                        }
                    }
                }

                int zl = zbh + (lane >> 2);
                float4 xa = make_float4(0, 0, 0, 0), xb = make_float4(0, 0, 0, 0);
                if (zl < zv)
                    xa = __ldg((const float4*)(x2 + (size_t)(z0t + zl) * 4));
                if (zl + 8 < zv)
                    xb = __ldg((const float4*)(x2 + (size_t)(z0t + zl + 8) * 4));
#pragma unroll
                for (int nt = 0; nt < 4; ++nt) {
                    __half2 hA = *(__half2*)(smc + OFF_ST + (uint32_t)tid * 64 +
                                             (uint32_t)(zh * 32 + nt * 8));
                    __half2 hB = *(__half2*)(smc + OFF_ST + (uint32_t)tid * 64 +
                                             (uint32_t)(zh * 32 + nt * 8 + 4));
                    float t0 = __low2float(hA), t1v = __high2float(hA);
                    float t2 = __low2float(hB), t3 = __high2float(hB);
                    int c = 32 * wn + 8 * nt + (lane & 3) * 2;
                    if (zl < zv) {
                        float* o = out + (size_t)(z0t + zl) * 512 + 128 + 3 * c;
                        *(float2*)(o) =
                            make_float2(fmaf(xa.y, t0, du3[0][nt][0]),
                                        fmaf(xa.z, t0, du3[1][nt][0]));
                        *(float2*)(o + 2) =
                            make_float2(fmaf(xa.w, t0, du3[2][nt][0]),
                                        fmaf(xa.y, t1v, du3[0][nt][1]));
                        *(float2*)(o + 4) =
                            make_float2(fmaf(xa.z, t1v, du3[1][nt][1]),
                                        fmaf(xa.w, t1v, du3[2][nt][1]));
                    }
                    if (zl + 8 < zv) {
                        float* o =
                            out + (size_t)(z0t + zl + 8) * 512 + 128 + 3 * c;
                        *(float2*)(o) =
                            make_float2(fmaf(xb.y, t2, du3[0][nt][2]),
                                        fmaf(xb.z, t2, du3[1][nt][2]));
                        *(float2*)(o + 2) =
                            make_float2(fmaf(xb.w, t2, du3[2][nt][2]),
                                        fmaf(xb.y, t3, du3[0][nt][3]));
                        *(float2*)(o + 4) =
                            make_float2(fmaf(xb.z, t3, du3[1][nt][3]),
                                        fmaf(xb.w, t3, du3[2][nt][3]));
                    }
                }
            }
            __syncthreads();
        }
    }
}

extern "C" void kernel_launch(void* const* d_in, const int* in_sizes, int n_in,
                              void* d_out, int out_size) {
    const float* x1 = (const float*)d_in[0];
    const float* x2 = (const float*)d_in[1];
    const float* w = (const float*)d_in[2];
    float* out = (float*)d_out;
    const int Z = in_sizes[0] / 512;
    const int NT = (Z + TZ - 1) / TZ;

    int dev = 0;
    cudaGetDevice(&dev);
    int sms = 148;
    cudaDeviceGetAttribute(&sms, cudaDevAttrMultiProcessorCount, dev);

    cudaFuncSetAttribute(tp_hmma14, cudaFuncAttributeMaxDynamicSharedMemorySize,
                         SMEM_BYTES);
    int grid = 2 * sms;
    if (grid > NT) grid = NT;
    int NA = (grid * 40) / 100;
    if (NA < 1) NA = 1;
    if (NA > grid - 1) NA = grid - 1;
    int NB = grid - NA;

    tp_hmma14<<<grid, NTH, SMEM_BYTES>>>(x1, x2, w, out, Z, NT, NA, NB);
}

// round 17
// speedup vs baseline: 1.0397x; 1.0078x over previous
#include <cuda_runtime.h>
#include <cuda_fp16.h>
#include <cstdint>

#define NTH 256
#define TZ 64

#define OFF_W 0
#define OFF_FA 65536
#define OFF_FB 32768
#define OFF_ST 98304
#define SMEM_BYTES 114688

static __device__ __forceinline__ uint32_t s2u(const void* p) {
    uint32_t a;
    asm("{ .reg .u64 t; cvta.to.shared.u64 t, %1; cvt.u32.u64 %0, t; }"
        : "=r"(a) : "l"(p));
    return a;
}

static __device__ __forceinline__ uint32_t pkh2(float a, float b) {
    __half2 h = __floats2half2_rn(a, b);
    return *reinterpret_cast<uint32_t*>(&h);
}

static __device__ __forceinline__ void ldsm4(uint32_t addr, uint32_t r[4]) {
    asm volatile("ldmatrix.sync.aligned.m8n8.x4.shared.b16 {%0,%1,%2,%3}, [%4];"
                 : "=r"(r[0]), "=r"(r[1]), "=r"(r[2]), "=r"(r[3])
                 : "r"(addr));
}

static __device__ __forceinline__ void mma16816(float d[4], const uint32_t a[4],
                                                uint32_t b0, uint32_t b1) {
    asm volatile(
        "mma.sync.aligned.m16n8k16.row.col.f32.f16.f16.f32 "
        "{%0,%1,%2,%3}, {%4,%5,%6,%7}, {%8,%9}, {%0,%1,%2,%3};"
        : "+f"(d[0]), "+f"(d[1]), "+f"(d[2]), "+f"(d[3])
        : "r"(a[0]), "r"(a[1]), "r"(a[2]), "r"(a[3]), "r"(b0), "r"(b1));
}

__global__ void __launch_bounds__(NTH, 2)
tp_hmma15(const float* __restrict__ x1, const float* __restrict__ x2,
          const float* __restrict__ wts, float* __restrict__ out,
          int Z, int NT, int NA, int NB) {
    extern __shared__ char smc[];
    const uint32_t sb = s2u(smc);
    const int tid = threadIdx.x;
    const int lane = tid & 31, wid = tid >> 5;
    const int zm = wid & 1, wn = wid >> 1;
    const bool roleA = (int)blockIdx.x < NA;
    const float inv16 = 0.0625f;
    const float c2 = 0.03608439182435161f;  // 1/(16*sqrt(3))

    // ---- weights into smem (fp16, [w][k], swizzled), SCALES FOLDED IN ----
    if (roleA) {
        for (int i = tid; i < 4096; i += NTH) {
            int w = i >> 5, c = i & 31;
            const float* src = (c < 16) ? wts : (wts + 49152);  // W0 / W3
            const float sc = (c < 16) ? inv16 : c2;
            int u0 = (c & 15) * 8;
            uint32_t h[4];
#pragma unroll
            for (int j = 0; j < 4; ++j)
                h[j] = pkh2(sc * src[(u0 + 2 * j) * 128 + w],
                            sc * src[(u0 + 2 * j + 1) * 128 + w]);
            *(uint4*)(smc + OFF_W + w * 512 + ((c ^ (w & 7)) << 4)) =
                make_uint4(h[0], h[1], h[2], h[3]);
        }
    } else {
        for (int i = tid; i < 2048; i += NTH) {
            int w = i >> 4, c = i & 15;
            int u0 = c * 8;
            const float* s1 = wts + 16384;  // W1
            const float* s2 = wts + 32768;  // W2
            uint32_t h1[4], h2[4];
#pragma unroll
            for (int j = 0; j < 4; ++j) {
                h1[j] = pkh2(inv16 * s1[(u0 + 2 * j) * 128 + w],
                             inv16 * s1[(u0 + 2 * j + 1) * 128 + w]);
                h2[j] = pkh2(inv16 * s2[(u0 + 2 * j) * 128 + w],
                             inv16 * s2[(u0 + 2 * j + 1) * 128 + w]);
            }
            uint32_t so = (uint32_t)(w * 256 + ((c ^ (w & 7)) << 4));
            *(uint4*)(smc + OFF_W + so) = make_uint4(h1[0], h1[1], h1[2], h1[3]);
            *(uint4*)(smc + OFF_W + 32768 + so) =
                make_uint4(h2[0], h2[1], h2[2], h2[3]);
        }
    }
    __syncthreads();

    if (roleA) {
        // ---- preload W0-half B fragments into registers ----
        uint32_t w0f[8][8];
        {
            const int brow0 = 32 * wn + ((lane >> 4) << 3) + (lane & 7);
            const int bch = (lane >> 3) & 1;
#pragma unroll
            for (int ks = 0; ks < 8; ++ks)
#pragma unroll
                for (int nb = 0; nb < 2; ++nb) {
                    int row = brow0 + 16 * nb;
                    ldsm4(sb + OFF_W + row * 512 +
                              (((ks * 2 + bch) ^ (row & 7)) << 4),
                          &w0f[ks][4 * nb]);
                }
        }
        const int zb = 32 * zm;
        for (int t = (int)blockIdx.x; t < NT; t += NA) {
            const int z0t = t * TZ;
            const int zv = min(TZ, Z - z0t);

            // a-part: k chunks 0..15 (f = x2.x * a; inv16 folded into W0)
#pragma unroll 2
            for (int it = 0; it < 4; ++it) {
                int i = tid + it * NTH;
                int z = i >> 4, c = i & 15;
                uint4 wv = make_uint4(0, 0, 0, 0);
                if (z < zv) {
                    float s = __ldg(x2 + (size_t)(z0t + z) * 4);
                    const float* ap = x1 + (size_t)(z0t + z) * 512 + 8 * c;
                    float4 p0 = *(const float4*)(ap);
                    float4 p1 = *(const float4*)(ap + 4);
                    wv = make_uint4(pkh2(s * p0.x, s * p0.y),
                                    pkh2(s * p0.z, s * p0.w),
                                    pkh2(s * p1.x, s * p1.y),
                                    pkh2(s * p1.z, s * p1.w));
                }
                *(uint4*)(smc + OFF_FA + z * 512 + ((c ^ (z & 7)) << 4)) = wv;
            }
            // b-part: k chunks 16..31 (f = B.v; c2 folded into W3)
#pragma unroll 2
            for (int it = 0; it < 4; ++it) {
                int i = tid + it * NTH;
                int z = i >> 4, c = (i & 15) + 16;
                uint4 wv = make_uint4(0, 0, 0, 0);
                if (z < zv) {
                    float4 xv = __ldg((const float4*)(x2 + (size_t)(z0t + z) * 4));
                    const float* bp =
                        x1 + (size_t)(z0t + z) * 512 + 128 + 24 * (c - 16);
                    float arr[24];
#pragma unroll
                    for (int q = 0; q < 6; ++q)
                        *(float4*)(arr + 4 * q) = *(const float4*)(bp + 4 * q);
                    float f[8];
#pragma unroll
                    for (int j = 0; j < 8; ++j)
                        f[j] = arr[3 * j] * xv.y + arr[3 * j + 1] * xv.z +
                               arr[3 * j + 2] * xv.w;
                    wv = make_uint4(pkh2(f[0], f[1]), pkh2(f[2], f[3]),
                                    pkh2(f[4], f[5]), pkh2(f[6], f[7]));
                }
                *(uint4*)(smc + OFF_FA + z * 512 + ((c ^ (z & 7)) << 4)) = wv;
            }
            __syncthreads();

            float d[2][4][4];
#pragma unroll
            for (int mt = 0; mt < 2; ++mt)
#pragma unroll
                for (int nt = 0; nt < 4; ++nt)
#pragma unroll
                    for (int r = 0; r < 4; ++r) d[mt][nt][r] = 0.0f;
            {
                const int arow0 = zb + (lane & 15);
                const int ach = lane >> 4;
                const int brow0 = 32 * wn + ((lane >> 4) << 3) + (lane & 7);
                const int bch = (lane >> 3) & 1;
#pragma unroll
                for (int ks = 0; ks < 8; ++ks) {
                    uint32_t a[2][4];
#pragma unroll
                    for (int mt = 0; mt < 2; ++mt) {
                        int row = arow0 + 16 * mt;
                        ldsm4(sb + OFF_FA + row * 512 +
                                  (((ks * 2 + ach) ^ (row & 7)) << 4),
                              a[mt]);
                    }
#pragma unroll
                    for (int mt = 0; mt < 2; ++mt)
#pragma unroll
                        for (int nt = 0; nt < 4; ++nt)
                            mma16816(d[mt][nt], a[mt],
                                     w0f[ks][(nt >> 1) * 4 + (nt & 1) * 2],
                                     w0f[ks][(nt >> 1) * 4 + (nt & 1) * 2 + 1]);
                }
#pragma unroll
                for (int ks = 8; ks < 16; ++ks) {
                    uint32_t a[2][4];
#pragma unroll
                    for (int mt = 0; mt < 2; ++mt) {
                        int row = arow0 + 16 * mt;
                        ldsm4(sb + OFF_FA + row * 512 +
                                  (((ks * 2 + ach) ^ (row & 7)) << 4),
                              a[mt]);
                    }
                    uint32_t b[2][4];
#pragma unroll
                    for (int nb = 0; nb < 2; ++nb) {
                        int row = brow0 + 16 * nb;
                        ldsm4(sb + OFF_W + row * 512 +
                                  (((ks * 2 + bch) ^ (row & 7)) << 4),
                              b[nb]);
                    }
#pragma unroll
                    for (int mt = 0; mt < 2; ++mt)
#pragma unroll
                        for (int nt = 0; nt < 4; ++nt)
                            mma16816(d[mt][nt], a[mt], b[nt >> 1][(nt & 1) * 2],
                                     b[nt >> 1][(nt & 1) * 2 + 1]);
                }
            }

#pragma unroll
            for (int mt = 0; mt < 2; ++mt) {
                int zl = zb + 16 * mt + (lane >> 2);
#pragma unroll
                for (int nt = 0; nt < 4; ++nt) {
                    int c = 32 * wn + 8 * nt + (lane & 3) * 2;
                    if (zl < zv)
                        *(float2*)(out + (size_t)(z0t + zl) * 512 + c) =
                            make_float2(d[mt][nt][0], d[mt][nt][1]);
                    if (zl + 8 < zv)
                        *(float2*)(out + (size_t)(z0t + zl + 8) * 512 + c) =
                            make_float2(d[mt][nt][2], d[mt][nt][3]);
                }
            }
            __syncthreads();
        }
    } else {
        // ---- preload W2 fragments (W2 smem dead afterwards) ----
        uint32_t w2f[8][8];
        {
            const uint32_t wb = sb + OFF_W + 32768;
            const int brow0 = 32 * wn + ((lane >> 4) << 3) + (lane & 7);
            const int bch = (lane >> 3) & 1;
#pragma unroll
            for (int ks = 0; ks < 8; ++ks)
#pragma unroll
                for (int nb = 0; nb < 2; ++nb) {
                    int row = brow0 + 16 * nb;
                    ldsm4(wb + row * 256 + (((ks * 2 + bch) ^ (row & 7)) << 4),
                          &w2f[ks][4 * nb]);
                }
        }
        __syncthreads();

        for (int t = (int)blockIdx.x - NA; t < NT; t += NB) {
            const int z0t = t * TZ;
            const int zv = min(TZ, Z - z0t);

            // ---- FUSED build: Fa = raw a (inv16 in W1); F_k = x2.x * b_k ----
#pragma unroll 1
            for (int it = 0; it < 4; ++it) {
                int i = tid + it * NTH;
                int z = i >> 4, c = i & 15;
                uint32_t so = (uint32_t)(z * 256 + ((c ^ (z & 7)) << 4));
                if (z < zv) {
                    const float* row = x1 + (size_t)(z0t + z) * 512;
                    const float* ap = row + 8 * c;
                    const float* bp = row + 128 + 24 * c;
                    float4 p0 = *(const float4*)(ap);
                    float4 p1 = *(const float4*)(ap + 4);
                    float arr[24];
#pragma unroll
                    for (int q = 0; q < 6; ++q)
                        *(float4*)(arr + 4 * q) = *(const float4*)(bp + 4 * q);
                    float s = __ldg(x2 + (size_t)(z0t + z) * 4);
                    *(uint4*)(smc + OFF_FB + so) =
                        make_uint4(pkh2(p0.x, p0.y), pkh2(p0.z, p0.w),
                                   pkh2(p1.x, p1.y), pkh2(p1.z, p1.w));
#pragma unroll
                    for (int m = 0; m < 24; ++m) arr[m] *= s;
#pragma unroll
                    for (int k = 0; k < 3; ++k)
                        *(uint4*)(smc + OFF_FB + 16384 * (1 + k) + so) =
                            make_uint4(pkh2(arr[k], arr[3 + k]),
                                       pkh2(arr[6 + k], arr[9 + k]),
                                       pkh2(arr[12 + k], arr[15 + k]),
                                       pkh2(arr[18 + k], arr[21 + k]));
                } else {
                    uint4 zz = make_uint4(0, 0, 0, 0);
                    *(uint4*)(smc + OFF_FB + so) = zz;
#pragma unroll
                    for (int k = 0; k < 3; ++k)
                        *(uint4*)(smc + OFF_FB + 16384 * (1 + k) + so) = zz;
                }
            }
            __syncthreads();

            // ---- dt for both z-halves, FUSED ks loop (W1 B-frags read once) ----
            {
                float dt[2][4][4];
#pragma unroll
                for (int zh = 0; zh < 2; ++zh)
#pragma unroll
                    for (int nt = 0; nt < 4; ++nt)
#pragma unroll
                        for (int r = 0; r < 4; ++r) dt[zh][nt][r] = 0.0f;
                const int ach = lane >> 4;
                const int brow0 = 32 * wn + ((lane >> 4) << 3) + (lane & 7);
                const int bch = (lane >> 3) & 1;
#pragma unroll
                for (int ks = 0; ks < 8; ++ks) {
                    uint32_t b[2][4];
#pragma unroll
                    for (int nb = 0; nb < 2; ++nb) {
                        int row = brow0 + 16 * nb;
                        ldsm4(sb + OFF_W + row * 256 +
                                  (((ks * 2 + bch) ^ (row & 7)) << 4),
                              b[nb]);
                    }
#pragma unroll
                    for (int zh = 0; zh < 2; ++zh) {
                        int arow = 32 * zh + 16 * zm + (lane & 15);
                        uint32_t a[4];
                        ldsm4(sb + OFF_FB + arow * 256 +
                                  (((ks * 2 + ach) ^ (arow & 7)) << 4),
                              a);
#pragma unroll
                        for (int nt = 0; nt < 4; ++nt)
                            mma16816(dt[zh][nt], a, b[nt >> 1][(nt & 1) * 2],
                                     b[nt >> 1][(nt & 1) * 2 + 1]);
                    }
                }
#pragma unroll
                for (int zh = 0; zh < 2; ++zh)
#pragma unroll
                    for (int nt = 0; nt < 4; ++nt) {
                        *(uint32_t*)(smc + OFF_ST + (uint32_t)tid * 64 +
                                     (uint32_t)(zh * 32 + nt * 8)) =
                            pkh2(dt[zh][nt][0], dt[zh][nt][1]);
                        *(uint32_t*)(smc + OFF_ST + (uint32_t)tid * 64 +
                                     (uint32_t)(zh * 32 + nt * 8 + 4)) =
                            pkh2(dt[zh][nt][2], dt[zh][nt][3]);
                    }
            }

            // ---- du3 per z-half with register-resident W2; contiguous stores ----
#pragma unroll 1
            for (int zh = 0; zh < 2; ++zh) {
                int zbh = 32 * zh + 16 * zm;
                float du3[3][4][4];
#pragma unroll
                for (int k = 0; k < 3; ++k)
#pragma unroll
                    for (int nt = 0; nt < 4; ++nt)
#pragma unroll
                        for (int r = 0; r < 4; ++r) du3[k][nt][r] = 0.0f;
                {
                    const int arow = zbh + (lane & 15);
                    const int ach = lane >> 4;
#pragma unroll
                    for (int ks = 0; ks < 8; ++ks) {
#pragma unroll
                        for (int k = 0; k < 3; ++k) {
                            uint32_t a[4];
                            ldsm4(sb + OFF_FB + 16384 * (1 + k) + arow * 256 +
                                      (((ks * 2 + ach) ^ (arow & 7)) << 4),
                                  a);
#pragma unroll
                            for (int nt = 0; nt < 4; ++nt)
                                mma16816(du3[k][nt], a,
                                         w2f[ks][(nt >> 1) * 4 + (nt & 1) * 2],
                                         w2f[ks][(nt >> 1) * 4 + (nt & 1) * 2 + 1]);
                        }
                    }
                }

                int zl = zbh + (lane >> 2);
                float4 xa = make_float4(0, 0, 0, 0), xb = make_float4(0, 0, 0, 0);
                if (zl < zv)
                    xa = __ldg((const float4*)(x2 + (size_t)(z0t + zl) * 4));
                if (zl + 8 < zv)
                    xb = __ldg((const float4*)(x2 + (size_t)(z0t + zl + 8) * 4));
#pragma unroll
                for (int nt = 0; nt < 4; ++nt) {
                    __half2 hA = *(__half2*)(smc + OFF_ST + (uint32_t)tid * 64 +
                                             (uint32_t)(zh * 32 + nt * 8));
                    __half2 hB = *(__half2*)(smc + OFF_ST + (uint32_t)tid * 64 +
                                             (uint32_t)(zh * 32 + nt * 8 + 4));
                    float t0 = __low2float(hA), t1v = __high2float(hA);
                    float t2 = __low2float(hB), t3 = __high2float(hB);
                    int c = 32 * wn + 8 * nt + (lane & 3) * 2;
                    if (zl < zv) {
                        float* o = out + (size_t)(z0t + zl) * 512 + 128 + 3 * c;
                        *(float2*)(o) =
                            make_float2(fmaf(xa.y, t0, du3[0][nt][0]),
                                        fmaf(xa.z, t0, du3[1][nt][0]));
                        *(float2*)(o + 2) =
                            make_float2(fmaf(xa.w, t0, du3[2][nt][0]),
                                        fmaf(xa.y, t1v, du3[0][nt][1]));
                        *(float2*)(o + 4) =
                            make_float2(fmaf(xa.z, t1v, du3[1][nt][1]),
                                        fmaf(xa.w, t1v, du3[2][nt][1]));
                    }
                    if (zl + 8 < zv) {
                        float* o =
                            out + (size_t)(z0t + zl + 8) * 512 + 128 + 3 * c;
                        *(float2*)(o) =
                            make_float2(fmaf(xb.y, t2, du3[0][nt][2]),
                                        fmaf(xb.z, t2, du3[1][nt][2]));
                        *(float2*)(o + 2) =
                            make_float2(fmaf(xb.w, t2, du3[2][nt][2]),
                                        fmaf(xb.y, t3, du3[0][nt][3]));
                        *(float2*)(o + 4) =
                            make_float2(fmaf(xb.z, t3, du3[1][nt][3]),
                                        fmaf(xb.w, t3, du3[2][nt][3]));
                    }
                }
            }
            __syncthreads();
        }
    }
}

extern "C" void kernel_launch(void* const* d_in, const int* in_sizes, int n_in,
                              void* d_out, int out_size) {
    const float* x1 = (const float*)d_in[0];
    const float* x2 = (const float*)d_in[1];
    const float* w = (const float*)d_in[2];
    float* out = (float*)d_out;
    const int Z = in_sizes[0] / 512;
    const int NT = (Z + TZ - 1) / TZ;

    int dev = 0;
    cudaGetDevice(&dev);
    int sms = 148;
    cudaDeviceGetAttribute(&sms, cudaDevAttrMultiProcessorCount, dev);

    cudaFuncSetAttribute(tp_hmma15, cudaFuncAttributeMaxDynamicSharedMemorySize,
                         SMEM_BYTES);
    int grid = 2 * sms;
    if (grid > NT) grid = NT;
    int NA = (grid * 40) / 100;
    if (NA < 1) NA = 1;
    if (NA > grid - 1) NA = grid - 1;
    int NB = grid - NA;

    tp_hmma15<<<grid, NTH, SMEM_BYTES>>>(x1, x2, w, out, Z, NT, NA, NB);
}